// round 2
// baseline (speedup 1.0000x reference)
#include <cuda_runtime.h>
#include <math.h>

#define SEQ_LEN 12
#define HD   128
#define EMB  64
#define KTOT 192           // EMB + HD
#define NJ   512           // 4*HD gate columns
#define MT   64            // pedestrians per block
#define NTH  512
#define ROWP 68            // padded SMEM row (floats); 272B rows keep 8/16B alignment
#define SMEM_BYTES ((KTOT * ROWP + MT * 2) * 4)

// Duplicated-pair weight layouts (built by prep kernel):
//   g_A[k*512 + u*4 + {wi,wi,wf,wf}]   g_B[k*512 + u*4 + {wg,wg,wo,wo}]
// so one LDG.128 per lane yields two ready {w,w} f32x2 operands.
__device__ __align__(16) float g_A[KTOT * NJ];
__device__ __align__(16) float g_B[KTOT * NJ];
__device__ float g_bias[NJ];

__global__ void prep_kernel(const float* __restrict__ w_ih,   // [512,64]
                            const float* __restrict__ w_hh,   // [512,128]
                            const float* __restrict__ b_ih,
                            const float* __restrict__ b_hh) {
    int idx = blockIdx.x * blockDim.x + threadIdx.x;
    if (idx < KTOT * NJ) {
        int k = idx / NJ, j = idx % NJ;
        int gate = j >> 7, u = j & 127;
        float w = (k < EMB) ? w_ih[j * EMB + k] : w_hh[j * HD + (k - EMB)];
        float* dst = (gate < 2) ? &g_A[k * NJ + u * 4 + gate * 2]
                                : &g_B[k * NJ + u * 4 + (gate - 2) * 2];
        dst[0] = w; dst[1] = w;
    }
    if (idx < NJ) g_bias[idx] = b_ih[idx] + b_hh[idx];
}

typedef unsigned long long u64;

__device__ __forceinline__ u64 ffma2(u64 a, u64 b, u64 c) {
    u64 d;
    asm("fma.rn.f32x2 %0, %1, %2, %3;" : "=l"(d) : "l"(a), "l"(b), "l"(c));
    return d;
}
__device__ __forceinline__ u64 pack2(float lo, float hi) {
    u64 d;
    asm("mov.b64 %0, {%1, %2};" : "=l"(d) : "f"(lo), "f"(hi));
    return d;
}
__device__ __forceinline__ float2 unpack2(u64 v) {
    float2 r;
    asm("mov.b64 {%0, %1}, %2;" : "=f"(r.x), "=f"(r.y) : "l"(v));
    return r;
}
__device__ __forceinline__ float tanh_ap(float x) {
    float y; asm("tanh.approx.f32 %0, %1;" : "=f"(y) : "f"(x)); return y;
}
__device__ __forceinline__ float sigm_ap(float x) {
    return fmaf(0.5f, tanh_ap(0.5f * x), 0.5f);
}

__global__ __launch_bounds__(NTH, 1)
void decoder_kernel(const float* __restrict__ lpr,   // last_pos_rel [N,2]
                    const float* __restrict__ h0,    // [N,128]
                    const float* __restrict__ c0,    // [N,128]
                    const float* __restrict__ w_se,  // [64,2]
                    const float* __restrict__ b_se,  // [64]
                    const float* __restrict__ w_hp,  // [2,128]
                    const float* __restrict__ b_hp,  // [2]
                    float* __restrict__ out,         // [12,N,2]
                    int N) {
    extern __shared__ __align__(16) float smem[];
    float (*act_s)[ROWP] = (float (*)[ROWP])smem;          // rows 0..63 dec_in, 64..191 h
    float (*rel_s)[2]    = (float (*)[2])(smem + KTOT * ROWP);

    const int tid  = threadIdx.x;
    const int wid  = tid >> 5;
    const int lane = tid & 31;
    const int u    = (wid & 3) * 32 + lane;   // hidden unit 0..127
    const int m0   = (wid >> 2) * 16;         // ped sub-group base 0/16/32/48
    const int pbase = blockIdx.x * MT;

    // ---- prologue: h0 into act_s rows 64..191 ----
    for (int i = tid; i < MT * HD; i += NTH) {
        int ml = i >> 7;
        int uu = i & 127;
        act_s[EMB + uu][ml] = h0[(size_t)(pbase + ml) * HD + uu];
    }
    // ---- dec_in0 = last_pos_rel @ w_se^T + b_se ----
    for (int i = tid; i < MT * EMB; i += NTH) {
        int ml = i >> 6;
        int e  = i & 63;
        float r0 = lpr[(size_t)(pbase + ml) * 2 + 0];
        float r1 = lpr[(size_t)(pbase + ml) * 2 + 1];
        act_s[e][ml] = fmaf(r0, w_se[e * 2 + 0], fmaf(r1, w_se[e * 2 + 1], b_se[e]));
    }
    // ---- cell state in registers ----
    float creg[16];
    #pragma unroll
    for (int m = 0; m < 16; m++)
        creg[m] = c0[(size_t)(pbase + m0 + m) * HD + u];

    const u64 bi2 = pack2(g_bias[u],          g_bias[u]);
    const u64 bf2 = pack2(g_bias[HD + u],     g_bias[HD + u]);
    const u64 bg2 = pack2(g_bias[2 * HD + u], g_bias[2 * HD + u]);
    const u64 bo2 = pack2(g_bias[3 * HD + u], g_bias[3 * HD + u]);

    const ulonglong2* __restrict__ wAp = (const ulonglong2*)g_A;
    const ulonglong2* __restrict__ wBp = (const ulonglong2*)g_B;

    __syncthreads();

    for (int t = 0; t < SEQ_LEN; t++) {
        // ---- main GEMM, packed over ped pairs: 32 FFMA2 per k ----
        u64 ai[8], af[8], ag[8], ao[8];
        #pragma unroll
        for (int p = 0; p < 8; p++) { ai[p] = bi2; af[p] = bf2; ag[p] = bg2; ao[p] = bo2; }

        #pragma unroll 4
        for (int k = 0; k < KTOT; k++) {
            ulonglong2 wa = wAp[k * (NJ / 4) + u];   // {wi,wi},{wf,wf}
            ulonglong2 wb = wBp[k * (NJ / 4) + u];   // {wg,wg},{wo,wo}
            const u64* a2 = (const u64*)&act_s[k][m0];  // 8 packed ped pairs (8B aligned)
            #pragma unroll
            for (int p = 0; p < 8; p++) {
                u64 a = a2[p];
                ai[p] = ffma2(wa.x, a, ai[p]);
                af[p] = ffma2(wa.y, a, af[p]);
                ag[p] = ffma2(wb.x, a, ag[p]);
                ao[p] = ffma2(wb.y, a, ao[p]);
            }
        }
        __syncthreads();   // everyone done reading old h

        // ---- LSTM cell update; write new h into act_s ----
        #pragma unroll
        for (int p = 0; p < 8; p++) {
            float2 fi = unpack2(ai[p]);
            float2 ff = unpack2(af[p]);
            float2 fg = unpack2(ag[p]);
            float2 fo = unpack2(ao[p]);
            {
                float c = fmaf(sigm_ap(ff.x), creg[2 * p],
                               sigm_ap(fi.x) * tanh_ap(fg.x));
                creg[2 * p] = c;
                act_s[EMB + u][m0 + 2 * p] = sigm_ap(fo.x) * tanh_ap(c);
            }
            {
                float c = fmaf(sigm_ap(ff.y), creg[2 * p + 1],
                               sigm_ap(fi.y) * tanh_ap(fg.y));
                creg[2 * p + 1] = c;
                act_s[EMB + u][m0 + 2 * p + 1] = sigm_ap(fo.y) * tanh_ap(c);
            }
        }
        __syncthreads();   // new h visible

        // ---- rel = h @ w_hp^T + b_hp ; write output ----
        if (tid < 2 * MT) {
            int d  = tid & 1;
            int ml = tid >> 1;
            float r = b_hp[d];
            const float* wh = w_hp + d * HD;
            #pragma unroll 8
            for (int uu = 0; uu < HD; uu++)
                r = fmaf(act_s[EMB + uu][ml], wh[uu], r);
            rel_s[ml][d] = r;
            out[(size_t)t * N * 2 + (size_t)(pbase + ml) * 2 + d] = r;
        }
        __syncthreads();

        // ---- next dec_in = rel @ w_se^T + b_se ----
        if (t < SEQ_LEN - 1) {
            for (int i = tid; i < MT * EMB; i += NTH) {
                int ml = i >> 6;
                int e  = i & 63;
                act_s[e][ml] = fmaf(rel_s[ml][0], w_se[e * 2 + 0],
                                fmaf(rel_s[ml][1], w_se[e * 2 + 1], b_se[e]));
            }
        }
        __syncthreads();
    }
}

extern "C" void kernel_launch(void* const* d_in, const int* in_sizes, int n_in,
                              void* d_out, int out_size) {
    const float* last_pos_rel = (const float*)d_in[1];
    const float* h0   = (const float*)d_in[2];
    const float* c0   = (const float*)d_in[3];
    const float* w_ih = (const float*)d_in[4];
    const float* w_hh = (const float*)d_in[5];
    const float* b_ih = (const float*)d_in[6];
    const float* b_hh = (const float*)d_in[7];
    const float* w_se = (const float*)d_in[8];
    const float* b_se = (const float*)d_in[9];
    const float* w_hp = (const float*)d_in[10];
    const float* b_hp = (const float*)d_in[11];
    float* out = (float*)d_out;

    int N = in_sizes[0] / 2;   // 65536

    cudaFuncSetAttribute(decoder_kernel,
                         cudaFuncAttributeMaxDynamicSharedMemorySize, SMEM_BYTES);

    prep_kernel<<<(KTOT * NJ + 255) / 256, 256>>>(w_ih, w_hh, b_ih, b_hh);
    decoder_kernel<<<N / MT, NTH, SMEM_BYTES>>>(
        last_pos_rel, h0, c0, w_se, b_se, w_hp, b_hp, out, N);
}

// round 6
// speedup vs baseline: 6.9123x; 6.9123x over previous
#include <cuda_runtime.h>
#include <cstdint>

#define SEQ_LEN 12
#define HD   128
#define NPB  64            // pedestrians per CTA
#define NTH  512
#define APITCH 136         // A-tile pitch in floats (phase-clean for permuted LDS.64)

// Fragment-ordered tf32 W_hh image: frag_id = (cw*8 + g*2 + nt)*16 + ks,
// lane l holds float2 {b0,b1}: j = g*128+cw*16+nt*8+(l>>2), k = ks*8+(l&3)+4*p
__device__ __align__(16) float g_Wf[65536];
__device__ __align__(16) float4 g_tab[512];

__device__ __forceinline__ float rtf32(float x) {
    uint32_t u = __float_as_uint(x);
    u = (u + 0x1000u) & 0xFFFFE000u;
    return __uint_as_float(u);
}
// k-permutation within an 8-k block: pairs (t, t+4) made adjacent
__device__ __forceinline__ int sigma_k(int k) {
    int kl = k & 7;
    return (k & ~7) + ((kl < 4) ? (2 * kl) : (2 * (kl - 4) + 1));
}

__global__ void prep_kernel(const float* __restrict__ w_ih, const float* __restrict__ w_hh,
                            const float* __restrict__ b_ih, const float* __restrict__ b_hh,
                            const float* __restrict__ w_se, const float* __restrict__ b_se,
                            const float* __restrict__ w_hp) {
    int idx = blockIdx.x * blockDim.x + threadIdx.x;
    if (idx < 65536) {
        int p   = idx & 1;
        int l   = (idx >> 1) & 31;
        int ks  = (idx >> 6) & 15;
        int nt  = (idx >> 10) & 1;
        int g   = (idx >> 11) & 3;
        int cw  = (idx >> 13) & 7;
        int j   = g * 128 + cw * 16 + nt * 8 + (l >> 2);
        int k   = ks * 8 + (l & 3) + 4 * p;        // PTX m16n8k8 B layout: b0 k=tig, b1 k=tig+4
        g_Wf[idx] = rtf32(w_hh[j * HD + k]);
    }
    if (idx < 512) {
        int j = idx;
        float bx = b_ih[j] + b_hh[j];
        float wy = 0.f, wz = 0.f;
        #pragma unroll 4
        for (int e = 0; e < 64; e++) {
            float w = w_ih[j * 64 + e];
            bx = fmaf(w, b_se[e], bx);
            wy = fmaf(w, w_se[e * 2 + 0], wy);
            wz = fmaf(w, w_se[e * 2 + 1], wz);
        }
        float ww = (j < 256) ? w_hp[j] : 0.f;   // tab[u].w=w_hp[0][u], tab[128+u].w=w_hp[1][u]
        g_tab[j] = make_float4(bx, wy, wz, ww);
    }
}

__device__ __forceinline__ float tanh_ap(float x) {
    float y; asm("tanh.approx.f32 %0, %1;" : "=f"(y) : "f"(x)); return y;
}
__device__ __forceinline__ float sigm_ap(float x) { return fmaf(0.5f, tanh_ap(0.5f * x), 0.5f); }

__device__ __forceinline__ void mma8(float& d0, float& d1, float& d2, float& d3,
                                     uint32_t a0, uint32_t a1, uint32_t a2, uint32_t a3,
                                     uint32_t b0, uint32_t b1) {
    asm volatile("mma.sync.aligned.m16n8k8.row.col.f32.tf32.tf32.f32 "
                 "{%0,%1,%2,%3},{%4,%5,%6,%7},{%8,%9},{%0,%1,%2,%3};"
                 : "+f"(d0), "+f"(d1), "+f"(d2), "+f"(d3)
                 : "r"(a0), "r"(a1), "r"(a2), "r"(a3), "r"(b0), "r"(b1));
}

__global__ __launch_bounds__(NTH, 1)
void decoder_kernel(const float* __restrict__ lpr, const float* __restrict__ h0,
                    const float* __restrict__ c0,  const float* __restrict__ b_hp,
                    float* __restrict__ out, int N) {
    __shared__ float  A_s[NPB][APITCH];    // h, tf32-rounded, k-permuted columns
    __shared__ float4 tab_s[512];
    __shared__ float2 rel_s[NPB];
    __shared__ float2 part_s[8][NPB];

    const int tid  = threadIdx.x;
    const int wid  = tid >> 5;
    const int lane = tid & 31;
    const int gid  = lane >> 2;       // group: A row / B n-col
    const int tig  = lane & 3;        // thread-in-group
    const int cw   = wid & 7;         // col-warp: u-range cw*16..+15, all 4 gates
    const int mt   = wid >> 3;        // m-tile: peds mt*32..+31
    const int m0   = mt * 32;
    const int pbase = blockIdx.x * NPB;

    // ---- prologue ----
    for (int i = tid; i < 512; i += NTH) tab_s[i] = g_tab[i];
    if (tid < NPB) rel_s[tid] = ((const float2*)lpr)[pbase + tid];
    for (int i = tid; i < NPB * HD; i += NTH) {
        int ml = i >> 7, u = i & 127;
        A_s[ml][sigma_k(u)] = rtf32(h0[(size_t)(pbase + ml) * HD + u]);
    }
    // creg[m2][rr][nt][cc]: ped = m0+m2*16+gid+rr*8 ; u = cw*16+nt*8+2*tig+cc (D layout)
    float creg[2][2][2][2];
    #pragma unroll
    for (int m2 = 0; m2 < 2; m2++)
        #pragma unroll
        for (int rr = 0; rr < 2; rr++) {
            int p = pbase + m0 + m2 * 16 + gid + rr * 8;
            #pragma unroll
            for (int nt = 0; nt < 2; nt++)
                #pragma unroll
                for (int cc = 0; cc < 2; cc++)
                    creg[m2][rr][nt][cc] = c0[(size_t)p * HD + cw * 16 + nt * 8 + 2 * tig + cc];
        }
    const float bhp0 = b_hp[0], bhp1 = b_hp[1];
    const float2* __restrict__ wf2 = (const float2*)g_Wf;
    __syncthreads();

    for (int t = 0; t < SEQ_LEN; t++) {
        // ---- gates = h @ Whh^T  (tf32 mma.sync) ----
        float acc[2][4][2][4];
        #pragma unroll
        for (int m2 = 0; m2 < 2; m2++)
            #pragma unroll
            for (int g = 0; g < 4; g++)
                #pragma unroll
                for (int nt = 0; nt < 2; nt++)
                    #pragma unroll
                    for (int q = 0; q < 4; q++) acc[m2][g][nt][q] = 0.f;

        #pragma unroll 2
        for (int ks = 0; ks < 16; ks++) {
            // A frags: permuted column 2*tig holds {k=tig, k=tig+4} -> a0=lo.x, a2=lo.y
            uint32_t a[2][4];
            #pragma unroll
            for (int m2 = 0; m2 < 2; m2++) {
                float2 lo = *(const float2*)&A_s[m0 + m2 * 16 + gid    ][ks * 8 + 2 * tig];
                float2 hi = *(const float2*)&A_s[m0 + m2 * 16 + gid + 8][ks * 8 + 2 * tig];
                a[m2][0] = __float_as_uint(lo.x); a[m2][2] = __float_as_uint(lo.y);
                a[m2][1] = __float_as_uint(hi.x); a[m2][3] = __float_as_uint(hi.y);
            }
            const int base = (cw * 128 + ks) * 32 + lane;
            #pragma unroll
            for (int g = 0; g < 4; g++)
                #pragma unroll
                for (int nt = 0; nt < 2; nt++) {
                    float2 b = __ldg(&wf2[base + ((g * 2 + nt) * 16) * 32]);
                    uint32_t b0 = __float_as_uint(b.x), b1 = __float_as_uint(b.y);
                    #pragma unroll
                    for (int m2 = 0; m2 < 2; m2++)
                        mma8(acc[m2][g][nt][0], acc[m2][g][nt][1],
                             acc[m2][g][nt][2], acc[m2][g][nt][3],
                             a[m2][0], a[m2][1], a[m2][2], a[m2][3], b0, b1);
                }
        }
        __syncthreads();   // all A reads done before h overwrite

        // ---- epilogue ----
        float2 relv[2][2];
        #pragma unroll
        for (int m2 = 0; m2 < 2; m2++)
            #pragma unroll
            for (int rr = 0; rr < 2; rr++)
                relv[m2][rr] = rel_s[m0 + m2 * 16 + gid + rr * 8];

        float pa0[2][2] = {{0.f,0.f},{0.f,0.f}}, pa1[2][2] = {{0.f,0.f},{0.f,0.f}};

        #pragma unroll
        for (int nt = 0; nt < 2; nt++)
            #pragma unroll
            for (int cc = 0; cc < 2; cc++) {
                const int u  = cw * 16 + nt * 8 + 2 * tig + cc;
                const int uc = cw * 16 + sigma_k(nt * 8 + 2 * tig + cc);  // permuted store col
                float4 tI = tab_s[u], tF = tab_s[128 + u], tG = tab_s[256 + u], tO = tab_s[384 + u];
                #pragma unroll
                for (int m2 = 0; m2 < 2; m2++)
                    #pragma unroll
                    for (int rr = 0; rr < 2; rr++) {
                        float2 rl = relv[m2][rr];
                        int q = rr * 2 + cc;
                        float gi = acc[m2][0][nt][q] + tI.x + rl.x * tI.y + rl.y * tI.z;
                        float gf = acc[m2][1][nt][q] + tF.x + rl.x * tF.y + rl.y * tF.z;
                        float gg = acc[m2][2][nt][q] + tG.x + rl.x * tG.y + rl.y * tG.z;
                        float go = acc[m2][3][nt][q] + tO.x + rl.x * tO.y + rl.y * tO.z;
                        float c  = fmaf(sigm_ap(gf), creg[m2][rr][nt][cc],
                                        sigm_ap(gi) * tanh_ap(gg));
                        creg[m2][rr][nt][cc] = c;
                        float h = sigm_ap(go) * tanh_ap(c);
                        A_s[m0 + m2 * 16 + gid + rr * 8][uc] = rtf32(h);
                        pa0[m2][rr] = fmaf(h, tI.w, pa0[m2][rr]);
                        pa1[m2][rr] = fmaf(h, tF.w, pa1[m2][rr]);
                    }
            }

        // reduce w_hp partials over the 4 tig lanes
        #pragma unroll
        for (int m2 = 0; m2 < 2; m2++)
            #pragma unroll
            for (int rr = 0; rr < 2; rr++) {
                float p0 = pa0[m2][rr], p1 = pa1[m2][rr];
                p0 += __shfl_xor_sync(0xFFFFFFFFu, p0, 1);
                p0 += __shfl_xor_sync(0xFFFFFFFFu, p0, 2);
                p1 += __shfl_xor_sync(0xFFFFFFFFu, p1, 1);
                p1 += __shfl_xor_sync(0xFFFFFFFFu, p1, 2);
                if (tig == 0)
                    part_s[cw][m0 + m2 * 16 + gid + rr * 8] = make_float2(p0, p1);
            }
        __syncthreads();

        if (tid < NPB) {
            float r0 = bhp0, r1 = bhp1;
            #pragma unroll
            for (int q = 0; q < 8; q++) {
                float2 v = part_s[q][tid];
                r0 += v.x; r1 += v.y;
            }
            rel_s[tid] = make_float2(r0, r1);
            ((float2*)out)[(size_t)t * N + pbase + tid] = make_float2(r0, r1);
        }
        __syncthreads();
    }
}

extern "C" void kernel_launch(void* const* d_in, const int* in_sizes, int n_in,
                              void* d_out, int out_size) {
    // order: last_pos, last_pos_rel, h0, c0, w_ih, w_hh, b_ih, b_hh, w_se, b_se, w_hp, b_hp
    const float* lpr  = (const float*)d_in[1];
    const float* h0   = (const float*)d_in[2];
    const float* c0   = (const float*)d_in[3];
    const float* w_ih = (const float*)d_in[4];
    const float* w_hh = (const float*)d_in[5];
    const float* b_ih = (const float*)d_in[6];
    const float* b_hh = (const float*)d_in[7];
    const float* w_se = (const float*)d_in[8];
    const float* b_se = (const float*)d_in[9];
    const float* w_hp = (const float*)d_in[10];
    const float* b_hp = (const float*)d_in[11];
    float* out = (float*)d_out;

    int N = in_sizes[0] / 2;   // 65536

    prep_kernel<<<65536 / 256, 256>>>(w_ih, w_hh, b_ih, b_hh, w_se, b_se, w_hp);
    decoder_kernel<<<N / NPB, NTH>>>(lpr, h0, c0, b_hp, out, N);
}